// round 9
// baseline (speedup 1.0000x reference)
#include <cuda_runtime.h>
#include <math.h>

#define HID   256
#define B_    16
#define T_    1024
#define S_    256
#define MMAX  5151
#define NSLOT 184
#define PW    4             // partial width per warp-step
#define MARG  9.0f          // tanh(9) = 1 - 3e-8 : saturation margin (x500 units)

typedef unsigned long long u64;

// -------- scratch (static device globals; no runtime allocation) ----------
__device__ float g_density[MMAX + 32];
__device__ float g_dsum;
__device__ float g_ctxw[B_ * HID];
__device__ float g_init[B_ * MMAX + 32];
__device__ float g_partial[(size_t)B_ * NSLOT * T_ * PW];

struct Tiles {
    int nt;
    int n;
    short tb[192];
    short ta[192];
};

__device__ __forceinline__ float sigmoidf_(float x) { return 1.0f / (1.0f + expf(-x)); }
__device__ __forceinline__ float tanh_fast(float x) {
    float y; asm("tanh.approx.f32 %0, %1;" : "=f"(y) : "f"(x)); return y;
}
__device__ __forceinline__ u64 pk2(float lo, float hi) {
    u64 r; asm("mov.b64 %0, {%1, %2};" : "=l"(r) : "f"(lo), "f"(hi)); return r;
}
__device__ __forceinline__ void upk2(u64 v, float& lo, float& hi) {
    asm("mov.b64 {%0, %1}, %2;" : "=f"(lo), "=f"(hi) : "l"(v));
}
__device__ __forceinline__ void ffma2(u64& d, u64 a, u64 b) {
    asm("fma.rn.f32x2 %0, %1, %2, %0;" : "+l"(d) : "l"(a), "l"(b));
}
__device__ __forceinline__ float warp_min(float v) {
#pragma unroll
    for (int o = 16; o > 0; o >>= 1) v = fminf(v, __shfl_xor_sync(0xffffffffu, v, o));
    return v;
}
__device__ __forceinline__ float warp_max(float v) {
#pragma unroll
    for (int o = 16; o > 0; o >>= 1) v = fmaxf(v, __shfl_xor_sync(0xffffffffu, v, o));
    return v;
}

// ---------------- K1: density MLP + fused encoder ctx ----------------------
// blocks [0, nDens): density (16 rows, packed f32x2 FFMA).
// blocks [nDens, nDens+16): encoder ctx for batch (bx - nDens), 2 cols/thread.
#define PADK 258
__global__ void __launch_bounds__(128)
k_dens_ctx(const float* __restrict__ mesh,
           const float* __restrict__ Win, const float* __restrict__ bin,
           const float* __restrict__ Wr,  const float* __restrict__ br,
           const float* __restrict__ Wout,const float* __restrict__ bout,
           const float* __restrict__ enc_in, const float* __restrict__ maskp,
           const float* __restrict__ Ws, const float* __restrict__ bs,
           const float* __restrict__ Wc, const float* __restrict__ bm,
           int M, int nDens)
{
    __shared__ float2 hP[8][PADK];
    __shared__ float  sB[16][128];
    __shared__ float  ctx_s[HID];
    const int tid = threadIdx.x;

    if (blockIdx.x >= nDens) {
        // ---------------- encoder ctx path ----------------
        int b = blockIdx.x - nDens;
        int ca = tid, cb = tid + 128;
        float w0a = Ws[ca], w1a = Ws[HID + ca], bba = bs[ca];
        float w0b = Ws[cb], w1b = Ws[HID + cb], bbb = bs[cb];
        float acca = 0.f, accb = 0.f, msum = 0.f;
        for (int s = 0; s < S_; ++s) {
            float mk = maskp[b * S_ + s];
            float e0 = enc_in[(b * S_ + s) * 2];
            float e1 = enc_in[(b * S_ + s) * 2 + 1];
            float va = fmaxf(fmaf(e0, w0a, fmaf(e1, w1a, bba)), 0.f);
            float vb = fmaxf(fmaf(e0, w0b, fmaf(e1, w1b, bbb)), 0.f);
            acca = fmaf(va, mk, acca);
            accb = fmaf(vb, mk, accb);
            msum += mk;
        }
        float inv = 1.0f / fmaxf(msum, 1.0f);
        ctx_s[ca] = acca * inv;
        ctx_s[cb] = accb * inv;
        __syncthreads();
        float cwa = bm[ca], cwb = bm[cb];
        for (int k = 0; k < HID; ++k) {
            float cx = ctx_s[k];
            cwa = fmaf(cx, Wc[k * HID + ca], cwa);
            cwb = fmaf(cx, Wc[k * HID + cb], cwb);
        }
        g_ctxw[b * HID + ca] = cwa;
        g_ctxw[b * HID + cb] = cwb;
        return;
    }

    // ---------------- density path ----------------
    const int c0  = 2 * tid, c1 = c0 + 1;
    const int r0  = blockIdx.x * 16;

    {
        float wa0 = Win[c0], wb0 = Win[HID + c0], bi0 = bin[c0];
        float wa1 = Win[c1], wb1 = Win[HID + c1], bi1 = bin[c1];
#pragma unroll
        for (int p = 0; p < 8; ++p) {
            float4 v;
            float be0 = 0.f, al0 = 0.f, be1 = 0.f, al1 = 0.f;
            int ra = r0 + 2 * p, rb = ra + 1;
            if (ra < M) { be0 = mesh[ra * 2]; al0 = mesh[ra * 2 + 1]; }
            if (rb < M) { be1 = mesh[rb * 2]; al1 = mesh[rb * 2 + 1]; }
            v.x = fmaxf(fmaf(be0, wa0, fmaf(al0, wb0, bi0)), 0.f);
            v.y = fmaxf(fmaf(be1, wa0, fmaf(al1, wb0, bi0)), 0.f);
            v.z = fmaxf(fmaf(be0, wa1, fmaf(al0, wb1, bi1)), 0.f);
            v.w = fmaxf(fmaf(be1, wa1, fmaf(al1, wb1, bi1)), 0.f);
            *(float4*)&hP[p][c0] = v;
        }
    }
    __syncthreads();

    for (int l = 0; l < 3; ++l) {
        u64 A0[8], A1[8];
        {
            float bb0 = br[l * HID + c0], bb1 = br[l * HID + c1];
            u64 p0 = pk2(bb0, bb0), p1 = pk2(bb1, bb1);
#pragma unroll
            for (int p = 0; p < 8; ++p) { A0[p] = p0; A1[p] = p1; }
        }
        const float* W = Wr + l * HID * HID;
#pragma unroll 4
        for (int k = 0; k < HID; k += 2) {
            float2 wA = *(const float2*)&W[k * HID + c0];
            float2 wB = *(const float2*)&W[(k + 1) * HID + c0];
            u64 wx0 = pk2(wA.x, wA.x), wy0 = pk2(wA.y, wA.y);
            u64 wx1 = pk2(wB.x, wB.x), wy1 = pk2(wB.y, wB.y);
#pragma unroll
            for (int p = 0; p < 8; ++p) {
                float4 h4 = *(const float4*)&hP[p][k];
                u64 hk  = pk2(h4.x, h4.y);
                u64 hk1 = pk2(h4.z, h4.w);
                ffma2(A0[p], hk,  wx0);
                ffma2(A1[p], hk,  wy0);
                ffma2(A0[p], hk1, wx1);
                ffma2(A1[p], hk1, wy1);
            }
        }
        __syncthreads();
#pragma unroll
        for (int p = 0; p < 8; ++p) {
            float4 h4 = *(const float4*)&hP[p][c0];
            float a, b;
            upk2(A0[p], a, b);
            h4.x += fmaxf(a, 0.f); h4.y += fmaxf(b, 0.f);
            upk2(A1[p], a, b);
            h4.z += fmaxf(a, 0.f); h4.w += fmaxf(b, 0.f);
            *(float4*)&hP[p][c0] = h4;
        }
        __syncthreads();
    }

    {
        float wo0 = Wout[c0], wo1 = Wout[c1];
#pragma unroll
        for (int p = 0; p < 8; ++p) {
            float4 h4 = *(const float4*)&hP[p][c0];
            sB[2 * p][tid]     = fmaf(h4.x, wo0, h4.z * wo1);
            sB[2 * p + 1][tid] = fmaf(h4.y, wo0, h4.w * wo1);
        }
    }
    __syncthreads();

    int warp = tid >> 5, lane = tid & 31;
    float bo = bout[0];
    for (int rr = warp; rr < 16; rr += 4) {
        float v = (sB[rr][lane] + sB[rr][lane + 32]) + (sB[rr][lane + 64] + sB[rr][lane + 96]);
#pragma unroll
        for (int o = 16; o > 0; o >>= 1) v += __shfl_xor_sync(0xffffffffu, v, o);
        if (lane == 0) {
            int row = r0 + rr;
            if (row < M) g_density[row] = sigmoidf_(v + bo);
        }
    }
}

// ---------------- K3: initial states (thread per (b,j)) + fused dsum ------
__global__ void __launch_bounds__(256)
k_init(const float* __restrict__ mesh,
       const float* __restrict__ Wm, const float* __restrict__ Wo,
       const float* __restrict__ bo,
       float* __restrict__ out_init, float* __restrict__ out_dens,
       float* __restrict__ out_mesh, int M, int nJ)
{
    __shared__ float4 sw4[HID];
    __shared__ float  scw[HID];
    __shared__ float  red[256];
    int tid = threadIdx.x;
    int b   = blockIdx.y;

    if (blockIdx.x == nJ) {
        // ---- dsum (one block, batch row 0 only) ----
        if (b != 0) return;
        float s = 0.f;
        for (int i = tid; i < M; i += 256) s += g_density[i];
        red[tid] = s;
        __syncthreads();
        for (int o = 128; o > 0; o >>= 1) {
            if (tid < o) red[tid] += red[tid + o];
            __syncthreads();
        }
        if (tid == 0) g_dsum = red[0];
        return;
    }

    for (int i = tid; i < HID; i += 256) {
        sw4[i] = make_float4(Wm[i], Wm[HID + i], Wm[2 * HID + i], Wo[i]);
        scw[i] = g_ctxw[b * HID + i];
    }
    __syncthreads();

    int j = blockIdx.x * 256 + tid;
    if (j >= M) return;

    float be = mesh[j * 2], al = mesh[j * 2 + 1], de = g_density[j];
    float a0 = 0.f, a1 = 0.f, a2 = 0.f, a3 = 0.f;
#pragma unroll 4
    for (int c = 0; c < HID; c += 4) {
        float4 w; float z;
        w = sw4[c + 0]; z = fmaxf(fmaf(be, w.x, fmaf(al, w.y, fmaf(de, w.z, scw[c + 0]))), 0.f); a0 = fmaf(z, w.w, a0);
        w = sw4[c + 1]; z = fmaxf(fmaf(be, w.x, fmaf(al, w.y, fmaf(de, w.z, scw[c + 1]))), 0.f); a1 = fmaf(z, w.w, a1);
        w = sw4[c + 2]; z = fmaxf(fmaf(be, w.x, fmaf(al, w.y, fmaf(de, w.z, scw[c + 2]))), 0.f); a2 = fmaf(z, w.w, a2);
        w = sw4[c + 3]; z = fmaxf(fmaf(be, w.x, fmaf(al, w.y, fmaf(de, w.z, scw[c + 3]))), 0.f); a3 = fmaf(z, w.w, a3);
    }
    float is = tanhf((a0 + a1) + (a2 + a3) + bo[0]);
    int wg = b * M + j;
    g_init[wg]           = is;
    out_init[wg]         = is;
    out_dens[wg]         = de;
    out_mesh[wg * 2]     = be;
    out_mesh[wg * 2 + 1] = al;
}

// ---------------- K4: relay scan — branch-free clean path, 2-step unroll --
__global__ void __launch_bounds__(256)
k_scan(const float* __restrict__ mesh, const float* __restrict__ dec, int M, Tiles tl)
{
    __shared__ float hs[T_];
    int tid = threadIdx.x, lane = tid & 31, warp = tid >> 5;
    int b = blockIdx.y, tg = blockIdx.x;

    for (int t = tid; t < T_; t += 256) hs[t] = dec[b * T_ + t] * 500.f;
    __syncthreads();

    int tile = tg * 8 + warp;
    if (tile >= tl.nt) return;

    const int n  = tl.n;
    const int tb = tl.tb[tile], ta = tl.ta[tile];

    int rib = lane >> 3, ria = lane & 7;
    int ib = tb * 4 + rib, ia = ta * 8 + ria;

    float a5, b5, de, s;
    float amin = 1e30f, amax = -1e30f, bmin = 1e30f, bmax = -1e30f;
    if (ib < n && ia < n && ia >= ib) {
        int j = ib * n - (ib * (ib - 1)) / 2 + (ia - ib);
        b5 = mesh[2 * j] * 500.f;
        a5 = mesh[2 * j + 1] * 500.f;
        de = g_density[j];
        s  = g_init[b * M + j];
        amin = a5; amax = a5; bmin = b5; bmax = b5;
    } else {
        a5 = 4000.f; b5 = -4000.f; de = 0.f; s = 0.f;
    }
    const float am  = warp_min(amin) - MARG, aM = warp_max(amax) + MARG;
    const float bmn = warp_min(bmin) - MARG, bM = warp_max(bmax) + MARG;

    float sd = de;
    sd += __shfl_xor_sync(0xffffffffu, sd, 16);
    sd += __shfl_xor_sync(0xffffffffu, sd, 8);
    sd += __shfl_xor_sync(0xffffffffu, sd, 4);
    float cur = de * s;
    cur += __shfl_xor_sync(0xffffffffu, cur, 16);
    cur += __shfl_xor_sync(0xffffffffu, cur, 8);
    cur += __shfl_xor_sync(0xffffffffu, cur, 4);

    float* outp = g_partial + ((size_t)(b * NSLOT + tile)) * (T_ * PW);
    int pend = 0;
    const bool doSt = (lane < 8);
    const bool hiSt = (lane & 4) != 0;

#pragma unroll 1
    for (int t = 0; t < T_; t += 2) {
        float2 h2 = *(const float2*)&hs[t];
        float curA;
        // ---- step t ----
        {
            float ht = h2.x;
            bool dirty = ((ht > am) & (ht < aM)) | ((ht > bmn) & (ht < bM));
            if (dirty) {
                float sv = s;
                sv = (pend > 0) ?  1.0f : sv;
                sv = (pend < 0) ? -1.0f : sv;
                pend = 0;
                if ((ht > am) & (ht < aM)) {
                    float wu = fmaf(0.5f, tanh_fast(ht - a5), 0.5f);
                    sv = fmaf(wu, 1.0f - sv, sv);
                } else {
                    sv = (ht > a5) ? 1.0f : sv;
                }
                if ((ht > bmn) & (ht < bM)) {
                    float wd = fmaf(0.5f, tanh_fast(b5 - ht), 0.5f);
                    sv = fmaf(wd, -1.0f - sv, sv);
                } else {
                    sv = (ht < b5) ? -1.0f : sv;
                }
                s = sv;
                float acc = de * sv;
                acc += __shfl_xor_sync(0xffffffffu, acc, 16);
                acc += __shfl_xor_sync(0xffffffffu, acc, 8);
                acc += __shfl_xor_sync(0xffffffffu, acc, 4);
                cur = acc;
            } else {
                bool up = ht > aM;
                bool dn = ht < bmn;
                pend = up ? 1 : (dn ? -1 : pend);
                cur  = up ? sd : (dn ? -sd : cur);
            }
            curA = cur;
        }
        // ---- step t+1 ----
        {
            float ht = h2.y;
            bool dirty = ((ht > am) & (ht < aM)) | ((ht > bmn) & (ht < bM));
            if (dirty) {
                float sv = s;
                sv = (pend > 0) ?  1.0f : sv;
                sv = (pend < 0) ? -1.0f : sv;
                pend = 0;
                if ((ht > am) & (ht < aM)) {
                    float wu = fmaf(0.5f, tanh_fast(ht - a5), 0.5f);
                    sv = fmaf(wu, 1.0f - sv, sv);
                } else {
                    sv = (ht > a5) ? 1.0f : sv;
                }
                if ((ht > bmn) & (ht < bM)) {
                    float wd = fmaf(0.5f, tanh_fast(b5 - ht), 0.5f);
                    sv = fmaf(wd, -1.0f - sv, sv);
                } else {
                    sv = (ht < b5) ? -1.0f : sv;
                }
                s = sv;
                float acc = de * sv;
                acc += __shfl_xor_sync(0xffffffffu, acc, 16);
                acc += __shfl_xor_sync(0xffffffffu, acc, 8);
                acc += __shfl_xor_sync(0xffffffffu, acc, 4);
                cur = acc;
            } else {
                bool up = ht > aM;
                bool dn = ht < bmn;
                pend = up ? 1 : (dn ? -1 : pend);
                cur  = up ? sd : (dn ? -sd : cur);
            }
        }
        // lanes 0-3 store step t planes, lanes 4-7 store step t+1 planes:
        // one contiguous 8-float transaction per 2 steps.
        float v = hiSt ? cur : curA;
        if (doSt) outp[lane] = v;
        outp += 8;
    }
}

// ---------------- K5: reduce partials, scales, b_out ----------------------
__global__ void __launch_bounds__(128)
k_final(const float* __restrict__ dec,
        const float* __restrict__ hr, const float* __restrict__ mr,
        const float* __restrict__ offr,
        float* __restrict__ out_b, float* __restrict__ out_m,
        int nt)
{
    int idx = blockIdx.x * 128 + threadIdx.x;     // 0 .. B*T-1
    int b = idx >> 10, t = idx & 1023;
    const float* base = g_partial + (size_t)b * NSLOT * (T_ * PW) + (size_t)t * PW;
    float s0 = 0.f, s1 = 0.f, s2 = 0.f, s3 = 0.f;
    float u0 = 0.f, u1 = 0.f, u2 = 0.f, u3 = 0.f;
    int tile = 0;
    for (; tile + 1 < nt; tile += 2) {
        float4 v = *(const float4*)(base + (size_t)tile * (T_ * PW));
        float4 w = *(const float4*)(base + (size_t)(tile + 1) * (T_ * PW));
        s0 += v.x; s1 += v.y; s2 += v.z; s3 += v.w;
        u0 += w.x; u1 += w.y; u2 += w.z; u3 += w.w;
    }
    if (tile < nt) {
        float4 v = *(const float4*)(base + (size_t)tile * (T_ * PW));
        s0 += v.x; s1 += v.y; s2 += v.z; s3 += v.w;
    }
    float sum = ((s0 + u0) + (s1 + u1)) + ((s2 + u2) + (s3 + u3));
    float m = sum / g_dsum;

    float hsc = 10.f * sigmoidf_(hr[0]);
    float msc = 10.f * sigmoidf_(mr[0]);
    float mof = fmaf(20.f, sigmoidf_(offr[0]), -10.f);

    float hv = dec[idx];
    out_b[idx] = fmaf(hsc, hv, fmaf(msc, m, mof));
    out_m[idx] = m;
}

// ---------------- host launcher -------------------------------------------
extern "C" void kernel_launch(void* const* d_in, const int* in_sizes, int n_in,
                              void* d_out, int out_size)
{
    const float* enc_in = (const float*)d_in[0];
    const float* dec    = (const float*)d_in[1];
    const float* maskp  = (const float*)d_in[2];
    const float* mesh   = (const float*)d_in[3];
    const float* dWin   = (const float*)d_in[4];
    const float* dbin   = (const float*)d_in[5];
    const float* dWr    = (const float*)d_in[6];
    const float* dbr    = (const float*)d_in[7];
    const float* dWout  = (const float*)d_in[8];
    const float* dbout  = (const float*)d_in[9];
    const float* eWs    = (const float*)d_in[10];
    const float* ebs    = (const float*)d_in[11];
    const float* eWm    = (const float*)d_in[12];
    const float* eWc    = (const float*)d_in[13];
    const float* ebm    = (const float*)d_in[14];
    const float* eWo    = (const float*)d_in[15];
    const float* ebo    = (const float*)d_in[16];
    const float* hr     = (const float*)d_in[17];
    const float* mr     = (const float*)d_in[18];
    const float* offr   = (const float*)d_in[19];

    const int M = in_sizes[3] / 2;   // 5151

    int n = 2;
    while (n * (n + 1) / 2 < M) ++n;   // -> 101

    // tile list: 4 beta-steps x 8 alpha-steps per tile
    Tiles tl;
    tl.n = n;
    tl.nt = 0;
    int ntb = (n + 3) / 4, nta = (n + 7) / 8;
    for (int tb = 0; tb < ntb; ++tb)
        for (int ta = 0; ta < nta; ++ta) {
            int ibmin = tb * 4;
            int iamax = ta * 8 + 7; if (iamax > n - 1) iamax = n - 1;
            if (iamax < ibmin) continue;
            if (tl.nt < 192) { tl.tb[tl.nt] = (short)tb; tl.ta[tl.nt] = (short)ta; tl.nt++; }
        }
    if (tl.nt > NSLOT) tl.nt = NSLOT;
    int groups = (tl.nt + 7) / 8;

    float* out      = (float*)d_out;
    float* out_b    = out;
    float* out_dens = out_b    + B_ * T_;
    float* out_m    = out_dens + B_ * M;
    float* out_init = out_m    + B_ * T_;
    float* out_mesh = out_init + B_ * M;

    int nDens = (M + 15) / 16;           // 322
    int nJ    = (M + 255) / 256;         // 21

    k_dens_ctx<<<nDens + B_, 128>>>(mesh, dWin, dbin, dWr, dbr, dWout, dbout,
                                    enc_in, maskp, eWs, ebs, eWc, ebm, M, nDens);
    k_init<<<dim3(nJ + 1, B_), 256>>>(mesh, eWm, eWo, ebo, out_init, out_dens, out_mesh, M, nJ);
    k_scan<<<dim3(groups, B_), 256>>>(mesh, dec, M, tl);
    k_final<<<(B_ * T_) / 128, 128>>>(dec, hr, mr, offr, out_b, out_m, tl.nt);

    (void)n_in; (void)out_size;
}

// round 13
// speedup vs baseline: 1.2224x; 1.2224x over previous
#include <cuda_runtime.h>
#include <math.h>

#define HID   256
#define B_    16
#define T_    1024
#define S_    256
#define MMAX  5151
#define NSLOT 184
#define MARG  9.0f          // tanh(9) = 1 - 3e-8 : saturation margin (x500 units)

typedef unsigned long long u64;

// -------- scratch (static device globals; no runtime allocation) ----------
__device__ float g_density[MMAX + 32];
__device__ float g_dsum;
__device__ float g_ctxw[B_ * HID];
__device__ float g_init[B_ * MMAX + 32];
__device__ float g_partial[(size_t)B_ * NSLOT * T_];   // ONE float per warp-step

struct Tiles {
    int nt;
    int n;
    short tb[192];
    short ta[192];
};

__device__ __forceinline__ float sigmoidf_(float x) { return 1.0f / (1.0f + expf(-x)); }
__device__ __forceinline__ float tanh_fast(float x) {
    float y; asm("tanh.approx.f32 %0, %1;" : "=f"(y) : "f"(x)); return y;
}
__device__ __forceinline__ u64 pk2(float lo, float hi) {
    u64 r; asm("mov.b64 %0, {%1, %2};" : "=l"(r) : "f"(lo), "f"(hi)); return r;
}
__device__ __forceinline__ void upk2(u64 v, float& lo, float& hi) {
    asm("mov.b64 {%0, %1}, %2;" : "=f"(lo), "=f"(hi) : "l"(v));
}
__device__ __forceinline__ void ffma2(u64& d, u64 a, u64 b) {
    asm("fma.rn.f32x2 %0, %1, %2, %0;" : "+l"(d) : "l"(a), "l"(b));
}
__device__ __forceinline__ float warp_min(float v) {
#pragma unroll
    for (int o = 16; o > 0; o >>= 1) v = fminf(v, __shfl_xor_sync(0xffffffffu, v, o));
    return v;
}
__device__ __forceinline__ float warp_max(float v) {
#pragma unroll
    for (int o = 16; o > 0; o >>= 1) v = fmaxf(v, __shfl_xor_sync(0xffffffffu, v, o));
    return v;
}
__device__ __forceinline__ float warp_sum(float v) {
#pragma unroll
    for (int o = 16; o > 0; o >>= 1) v += __shfl_xor_sync(0xffffffffu, v, o);
    return v;
}

// ---------------- K1: density MLP + fused encoder ctx ----------------------
#define PADK 258
__global__ void __launch_bounds__(128)
k_dens_ctx(const float* __restrict__ mesh,
           const float* __restrict__ Win, const float* __restrict__ bin,
           const float* __restrict__ Wr,  const float* __restrict__ br,
           const float* __restrict__ Wout,const float* __restrict__ bout,
           const float* __restrict__ enc_in, const float* __restrict__ maskp,
           const float* __restrict__ Ws, const float* __restrict__ bs,
           const float* __restrict__ Wc, const float* __restrict__ bm,
           int M, int nDens)
{
    __shared__ float2 hP[8][PADK];
    __shared__ float  sB[16][128];
    __shared__ float  ctx_s[HID];
    const int tid = threadIdx.x;

    if (blockIdx.x >= nDens) {
        // ---------------- encoder ctx path ----------------
        int b = blockIdx.x - nDens;
        int ca = tid, cb = tid + 128;
        float w0a = Ws[ca], w1a = Ws[HID + ca], bba = bs[ca];
        float w0b = Ws[cb], w1b = Ws[HID + cb], bbb = bs[cb];
        float acca = 0.f, accb = 0.f, msum = 0.f;
        for (int s = 0; s < S_; ++s) {
            float mk = maskp[b * S_ + s];
            float e0 = enc_in[(b * S_ + s) * 2];
            float e1 = enc_in[(b * S_ + s) * 2 + 1];
            float va = fmaxf(fmaf(e0, w0a, fmaf(e1, w1a, bba)), 0.f);
            float vb = fmaxf(fmaf(e0, w0b, fmaf(e1, w1b, bbb)), 0.f);
            acca = fmaf(va, mk, acca);
            accb = fmaf(vb, mk, accb);
            msum += mk;
        }
        float inv = 1.0f / fmaxf(msum, 1.0f);
        ctx_s[ca] = acca * inv;
        ctx_s[cb] = accb * inv;
        __syncthreads();
        float cwa = bm[ca], cwb = bm[cb];
        for (int k = 0; k < HID; ++k) {
            float cx = ctx_s[k];
            cwa = fmaf(cx, Wc[k * HID + ca], cwa);
            cwb = fmaf(cx, Wc[k * HID + cb], cwb);
        }
        g_ctxw[b * HID + ca] = cwa;
        g_ctxw[b * HID + cb] = cwb;
        return;
    }

    // ---------------- density path ----------------
    const int c0  = 2 * tid, c1 = c0 + 1;
    const int r0  = blockIdx.x * 16;

    {
        float wa0 = Win[c0], wb0 = Win[HID + c0], bi0 = bin[c0];
        float wa1 = Win[c1], wb1 = Win[HID + c1], bi1 = bin[c1];
#pragma unroll
        for (int p = 0; p < 8; ++p) {
            float4 v;
            float be0 = 0.f, al0 = 0.f, be1 = 0.f, al1 = 0.f;
            int ra = r0 + 2 * p, rb = ra + 1;
            if (ra < M) { be0 = mesh[ra * 2]; al0 = mesh[ra * 2 + 1]; }
            if (rb < M) { be1 = mesh[rb * 2]; al1 = mesh[rb * 2 + 1]; }
            v.x = fmaxf(fmaf(be0, wa0, fmaf(al0, wb0, bi0)), 0.f);
            v.y = fmaxf(fmaf(be1, wa0, fmaf(al1, wb0, bi0)), 0.f);
            v.z = fmaxf(fmaf(be0, wa1, fmaf(al0, wb1, bi1)), 0.f);
            v.w = fmaxf(fmaf(be1, wa1, fmaf(al1, wb1, bi1)), 0.f);
            *(float4*)&hP[p][c0] = v;
        }
    }
    __syncthreads();

    for (int l = 0; l < 3; ++l) {
        u64 A0[8], A1[8];
        {
            float bb0 = br[l * HID + c0], bb1 = br[l * HID + c1];
            u64 p0 = pk2(bb0, bb0), p1 = pk2(bb1, bb1);
#pragma unroll
            for (int p = 0; p < 8; ++p) { A0[p] = p0; A1[p] = p1; }
        }
        const float* W = Wr + l * HID * HID;
#pragma unroll 4
        for (int k = 0; k < HID; k += 2) {
            float2 wA = *(const float2*)&W[k * HID + c0];
            float2 wB = *(const float2*)&W[(k + 1) * HID + c0];
            u64 wx0 = pk2(wA.x, wA.x), wy0 = pk2(wA.y, wA.y);
            u64 wx1 = pk2(wB.x, wB.x), wy1 = pk2(wB.y, wB.y);
#pragma unroll
            for (int p = 0; p < 8; ++p) {
                float4 h4 = *(const float4*)&hP[p][k];
                u64 hk  = pk2(h4.x, h4.y);
                u64 hk1 = pk2(h4.z, h4.w);
                ffma2(A0[p], hk,  wx0);
                ffma2(A1[p], hk,  wy0);
                ffma2(A0[p], hk1, wx1);
                ffma2(A1[p], hk1, wy1);
            }
        }
        __syncthreads();
#pragma unroll
        for (int p = 0; p < 8; ++p) {
            float4 h4 = *(const float4*)&hP[p][c0];
            float a, b;
            upk2(A0[p], a, b);
            h4.x += fmaxf(a, 0.f); h4.y += fmaxf(b, 0.f);
            upk2(A1[p], a, b);
            h4.z += fmaxf(a, 0.f); h4.w += fmaxf(b, 0.f);
            *(float4*)&hP[p][c0] = h4;
        }
        __syncthreads();
    }

    {
        float wo0 = Wout[c0], wo1 = Wout[c1];
#pragma unroll
        for (int p = 0; p < 8; ++p) {
            float4 h4 = *(const float4*)&hP[p][c0];
            sB[2 * p][tid]     = fmaf(h4.x, wo0, h4.z * wo1);
            sB[2 * p + 1][tid] = fmaf(h4.y, wo0, h4.w * wo1);
        }
    }
    __syncthreads();

    int warp = tid >> 5, lane = tid & 31;
    float bo = bout[0];
    for (int rr = warp; rr < 16; rr += 4) {
        float v = (sB[rr][lane] + sB[rr][lane + 32]) + (sB[rr][lane + 64] + sB[rr][lane + 96]);
        v = warp_sum(v);
        if (lane == 0) {
            int row = r0 + rr;
            if (row < M) g_density[row] = sigmoidf_(v + bo);
        }
    }
}

// ---------------- K3: initial states (thread per (b,j)) + fused dsum ------
__global__ void __launch_bounds__(256)
k_init(const float* __restrict__ mesh,
       const float* __restrict__ Wm, const float* __restrict__ Wo,
       const float* __restrict__ bo,
       float* __restrict__ out_init, float* __restrict__ out_dens,
       float* __restrict__ out_mesh, int M, int nJ)
{
    __shared__ float4 sw4[HID];
    __shared__ float  scw[HID];
    __shared__ float  red[256];
    int tid = threadIdx.x;
    int b   = blockIdx.y;

    if (blockIdx.x == nJ) {
        if (b != 0) return;
        float s = 0.f;
        for (int i = tid; i < M; i += 256) s += g_density[i];
        red[tid] = s;
        __syncthreads();
        for (int o = 128; o > 0; o >>= 1) {
            if (tid < o) red[tid] += red[tid + o];
            __syncthreads();
        }
        if (tid == 0) g_dsum = red[0];
        return;
    }

    for (int i = tid; i < HID; i += 256) {
        sw4[i] = make_float4(Wm[i], Wm[HID + i], Wm[2 * HID + i], Wo[i]);
        scw[i] = g_ctxw[b * HID + i];
    }
    __syncthreads();

    int j = blockIdx.x * 256 + tid;
    if (j >= M) return;

    float be = mesh[j * 2], al = mesh[j * 2 + 1], de = g_density[j];
    float a0 = 0.f, a1 = 0.f, a2 = 0.f, a3 = 0.f;
#pragma unroll 4
    for (int c = 0; c < HID; c += 4) {
        float4 w; float z;
        w = sw4[c + 0]; z = fmaxf(fmaf(be, w.x, fmaf(al, w.y, fmaf(de, w.z, scw[c + 0]))), 0.f); a0 = fmaf(z, w.w, a0);
        w = sw4[c + 1]; z = fmaxf(fmaf(be, w.x, fmaf(al, w.y, fmaf(de, w.z, scw[c + 1]))), 0.f); a1 = fmaf(z, w.w, a1);
        w = sw4[c + 2]; z = fmaxf(fmaf(be, w.x, fmaf(al, w.y, fmaf(de, w.z, scw[c + 2]))), 0.f); a2 = fmaf(z, w.w, a2);
        w = sw4[c + 3]; z = fmaxf(fmaf(be, w.x, fmaf(al, w.y, fmaf(de, w.z, scw[c + 3]))), 0.f); a3 = fmaf(z, w.w, a3);
    }
    float is = tanhf((a0 + a1) + (a2 + a3) + bo[0]);
    int wg = b * M + j;
    g_init[wg]           = is;
    out_init[wg]         = is;
    out_dens[wg]         = de;
    out_mesh[wg * 2]     = be;
    out_mesh[wg * 2 + 1] = al;
}

// ---------------- K4: relay scan — full warp-reduce, 1 float/warp-step ----
// Clean steps keep `cur` fully reduced for free (sd is full); dirty steps
// (~17%) pay a 5-shfl reduce. Lane 0 emits one STG.128 per 4 steps.
__global__ void __launch_bounds__(256)
k_scan(const float* __restrict__ mesh, const float* __restrict__ dec, int M, Tiles tl)
{
    __shared__ float hs[T_];
    int tid = threadIdx.x, lane = tid & 31, warp = tid >> 5;
    int b = blockIdx.y, tg = blockIdx.x;

    for (int t = tid; t < T_; t += 256) hs[t] = dec[b * T_ + t] * 500.f;
    __syncthreads();

    int tile = tg * 8 + warp;
    if (tile >= tl.nt) return;

    const int n  = tl.n;
    const int tb = tl.tb[tile], ta = tl.ta[tile];

    int rib = lane >> 3, ria = lane & 7;
    int ib = tb * 4 + rib, ia = ta * 8 + ria;

    float a5, b5, de, s;
    float amin = 1e30f, amax = -1e30f, bmin = 1e30f, bmax = -1e30f;
    if (ib < n && ia < n && ia >= ib) {
        int j = ib * n - (ib * (ib - 1)) / 2 + (ia - ib);
        b5 = mesh[2 * j] * 500.f;
        a5 = mesh[2 * j + 1] * 500.f;
        de = g_density[j];
        s  = g_init[b * M + j];
        amin = a5; amax = a5; bmin = b5; bmax = b5;
    } else {
        a5 = 4000.f; b5 = -4000.f; de = 0.f; s = 0.f;
    }
    const float am  = warp_min(amin) - MARG, aM = warp_max(amax) + MARG;
    const float bmn = warp_min(bmin) - MARG, bM = warp_max(bmax) + MARG;

    const float sd = warp_sum(de);          // fully reduced
    float cur = warp_sum(de * s);           // fully reduced

    float* outp = g_partial + ((size_t)(b * NSLOT + tile)) * T_;
    int pend = 0;

#define SCAN_STEP(HT, QOUT)                                                   \
    {                                                                         \
        float ht_ = (HT);                                                     \
        bool inA_ = (ht_ > am) & (ht_ < aM);                                  \
        bool inB_ = (ht_ > bmn) & (ht_ < bM);                                 \
        if (inA_ | inB_) {                                                    \
            float sv_ = s;                                                    \
            sv_ = (pend > 0) ?  1.0f : sv_;                                   \
            sv_ = (pend < 0) ? -1.0f : sv_;                                   \
            pend = 0;                                                         \
            if (inA_) {                                                       \
                float wu_ = fmaf(0.5f, tanh_fast(ht_ - a5), 0.5f);            \
                sv_ = fmaf(wu_, 1.0f - sv_, sv_);                             \
            } else {                                                          \
                sv_ = (ht_ > a5) ? 1.0f : sv_;                                \
            }                                                                 \
            if (inB_) {                                                       \
                float wd_ = fmaf(0.5f, tanh_fast(b5 - ht_), 0.5f);            \
                sv_ = fmaf(wd_, -1.0f - sv_, sv_);                            \
            } else {                                                          \
                sv_ = (ht_ < b5) ? -1.0f : sv_;                               \
            }                                                                 \
            s = sv_;                                                          \
            float acc_ = de * sv_;                                            \
            acc_ += __shfl_xor_sync(0xffffffffu, acc_, 16);                   \
            acc_ += __shfl_xor_sync(0xffffffffu, acc_, 8);                    \
            acc_ += __shfl_xor_sync(0xffffffffu, acc_, 4);                    \
            acc_ += __shfl_xor_sync(0xffffffffu, acc_, 2);                    \
            acc_ += __shfl_xor_sync(0xffffffffu, acc_, 1);                    \
            cur = acc_;                                                       \
        } else {                                                              \
            bool up_ = ht_ > aM;                                              \
            bool dn_ = ht_ < bmn;                                             \
            pend = up_ ? 1 : (dn_ ? -1 : pend);                               \
            cur  = up_ ? sd : (dn_ ? -sd : cur);                              \
        }                                                                     \
        QOUT = cur;                                                           \
    }

#pragma unroll 1
    for (int t = 0; t < T_; t += 4) {
        float4 h4 = *(const float4*)&hs[t];
        float4 q;
        SCAN_STEP(h4.x, q.x)
        SCAN_STEP(h4.y, q.y)
        SCAN_STEP(h4.z, q.z)
        SCAN_STEP(h4.w, q.w)
        if (lane == 0) *(float4*)(outp + t) = q;
    }
#undef SCAN_STEP
}

// ---------------- K5: reduce partials (coalesced), scales, b_out ----------
__global__ void __launch_bounds__(64)
k_final(const float* __restrict__ dec,
        const float* __restrict__ hr, const float* __restrict__ mr,
        const float* __restrict__ offr,
        float* __restrict__ out_b, float* __restrict__ out_m,
        int nt)
{
    int idx = blockIdx.x * 64 + threadIdx.x;      // 0 .. B*T-1
    int b = idx >> 10, t = idx & 1023;
    const float* base = g_partial + (size_t)(b * NSLOT) * T_ + t;
    float s0 = 0.f, s1 = 0.f, s2 = 0.f, s3 = 0.f;
    int tile = 0;
    for (; tile + 3 < nt; tile += 4) {
        s0 += base[(size_t)(tile + 0) * T_];
        s1 += base[(size_t)(tile + 1) * T_];
        s2 += base[(size_t)(tile + 2) * T_];
        s3 += base[(size_t)(tile + 3) * T_];
    }
    for (; tile < nt; ++tile) s0 += base[(size_t)tile * T_];
    float sum = (s0 + s1) + (s2 + s3);
    float m = sum / g_dsum;

    float hsc = 10.f * sigmoidf_(hr[0]);
    float msc = 10.f * sigmoidf_(mr[0]);
    float mof = fmaf(20.f, sigmoidf_(offr[0]), -10.f);

    float hv = dec[idx];
    out_b[idx] = fmaf(hsc, hv, fmaf(msc, m, mof));
    out_m[idx] = m;
}

// ---------------- host launcher -------------------------------------------
extern "C" void kernel_launch(void* const* d_in, const int* in_sizes, int n_in,
                              void* d_out, int out_size)
{
    const float* enc_in = (const float*)d_in[0];
    const float* dec    = (const float*)d_in[1];
    const float* maskp  = (const float*)d_in[2];
    const float* mesh   = (const float*)d_in[3];
    const float* dWin   = (const float*)d_in[4];
    const float* dbin   = (const float*)d_in[5];
    const float* dWr    = (const float*)d_in[6];
    const float* dbr    = (const float*)d_in[7];
    const float* dWout  = (const float*)d_in[8];
    const float* dbout  = (const float*)d_in[9];
    const float* eWs    = (const float*)d_in[10];
    const float* ebs    = (const float*)d_in[11];
    const float* eWm    = (const float*)d_in[12];
    const float* eWc    = (const float*)d_in[13];
    const float* ebm    = (const float*)d_in[14];
    const float* eWo    = (const float*)d_in[15];
    const float* ebo    = (const float*)d_in[16];
    const float* hr     = (const float*)d_in[17];
    const float* mr     = (const float*)d_in[18];
    const float* offr   = (const float*)d_in[19];

    const int M = in_sizes[3] / 2;   // 5151

    int n = 2;
    while (n * (n + 1) / 2 < M) ++n;   // -> 101

    // tile list: 4 beta-steps x 8 alpha-steps per tile
    Tiles tl;
    tl.n = n;
    tl.nt = 0;
    int ntb = (n + 3) / 4, nta = (n + 7) / 8;
    for (int tb = 0; tb < ntb; ++tb)
        for (int ta = 0; ta < nta; ++ta) {
            int ibmin = tb * 4;
            int iamax = ta * 8 + 7; if (iamax > n - 1) iamax = n - 1;
            if (iamax < ibmin) continue;
            if (tl.nt < 192) { tl.tb[tl.nt] = (short)tb; tl.ta[tl.nt] = (short)ta; tl.nt++; }
        }
    if (tl.nt > NSLOT) tl.nt = NSLOT;
    int groups = (tl.nt + 7) / 8;

    float* out      = (float*)d_out;
    float* out_b    = out;
    float* out_dens = out_b    + B_ * T_;
    float* out_m    = out_dens + B_ * M;
    float* out_init = out_m    + B_ * T_;
    float* out_mesh = out_init + B_ * M;

    int nDens = (M + 15) / 16;           // 322
    int nJ    = (M + 255) / 256;         // 21

    k_dens_ctx<<<nDens + B_, 128>>>(mesh, dWin, dbin, dWr, dbr, dWout, dbout,
                                    enc_in, maskp, eWs, ebs, eWc, ebm, M, nDens);
    k_init<<<dim3(nJ + 1, B_), 256>>>(mesh, eWm, eWo, ebo, out_init, out_dens, out_mesh, M, nJ);
    k_scan<<<dim3(groups, B_), 256>>>(mesh, dec, M, tl);
    k_final<<<(B_ * T_) / 64, 64>>>(dec, hr, mr, offr, out_b, out_m, tl.nt);

    (void)n_in; (void)out_size;
}